// round 1
// baseline (speedup 1.0000x reference)
#include <cuda_runtime.h>

// RoIAlign: features (2,256,8,64,64) f32, rois (512,5) f32
// out (512,256,8,7,7) f32
//
// Kernel 1: precompute per-(roi,ph,pw) bilinear table (25088 entries).
// Kernel 2: one thread per output element; 4-corner gather + weighted sum.

#define C_   256
#define T_   8
#define H_   64
#define W_   64
#define R_   512
#define S_   49            // 7*7 bins
#define BATCH_STRIDE (C_*T_*H_*W_)   // 8388608
#define TAB  (R_*S_)                 // 25088
#define OUT_TOTAL (R_*C_*T_*S_)      // 51380224

// Scratch (no allocation allowed): 25088 * 32 B = 802816 B
__device__ float4 g_w[TAB];
__device__ int4   g_off[TAB];

__global__ void bin_table_kernel(const float* __restrict__ rois) {
    int i = blockIdx.x * blockDim.x + threadIdx.x;
    if (i >= TAB) return;
    int r  = i / S_;
    int s  = i - r * S_;
    int ph = s / 7;
    int pw = s - ph * 7;

    const float* roi = rois + r * 5;
    int   b  = (int)roi[0];
    float x1 = roi[1] * 0.0625f;
    float y1 = roi[2] * 0.0625f;
    float x2 = roi[3] * 0.0625f;
    float y2 = roi[4] * 0.0625f;

    float roi_w = fmaxf(x2 - x1, 1.0f);
    float roi_h = fmaxf(y2 - y1, 1.0f);
    float bin_w = roi_w / 7.0f;
    float bin_h = roi_h / 7.0f;

    float xs = x1 + ((float)pw + 0.5f) * bin_w;
    float ys = y1 + ((float)ph + 0.5f) * bin_h;
    xs = fminf(fmaxf(xs, 0.0f), 63.0f);
    ys = fminf(fmaxf(ys, 0.0f), 63.0f);

    int x0  = (int)floorf(xs);
    int y0  = (int)floorf(ys);
    int x1i = min(x0 + 1, W_ - 1);
    int y1i = min(y0 + 1, H_ - 1);

    float wx = xs - (float)x0;
    float wy = ys - (float)y0;
    float omx = 1.0f - wx;
    float omy = 1.0f - wy;

    g_w[i] = make_float4(omy * omx, omy * wx, wy * omx, wy * wx);

    int idx00 = b * BATCH_STRIDE + y0 * W_ + x0;
    int dx    = x1i - x0;          // 0 or 1
    int dyW   = (y1i - y0) * W_;   // 0 or 64
    g_off[i] = make_int4(idx00, dx, dyW, dyW + dx);
}

__global__ void __launch_bounds__(256) roi_align_kernel(
    const float* __restrict__ features,
    float* __restrict__ out)
{
    unsigned idx = blockIdx.x * 256u + threadIdx.x;   // exact multiple, no guard
    unsigned ctr = idx / 49u;                          // (r*2048 + ct)
    unsigned s   = idx - ctr * 49u;
    unsigned r   = ctr >> 11;
    unsigned ct  = ctr & 2047u;                        // c*8 + t; slice stride 4096 floats
    unsigned ti  = r * 49u + s;

    float4 w = g_w[ti];
    int4   o = g_off[ti];

    const float* base = features + (long)o.x + ((long)ct << 12);
    float f00 = __ldg(base);
    float f01 = __ldg(base + o.y);
    float f10 = __ldg(base + o.z);
    float f11 = __ldg(base + o.w);

    out[idx] = w.x * f00 + w.y * f01 + w.z * f10 + w.w * f11;
}

extern "C" void kernel_launch(void* const* d_in, const int* in_sizes, int n_in,
                              void* d_out, int out_size) {
    const float* features = (const float*)d_in[0];
    const float* rois     = (const float*)d_in[1];
    float* out            = (float*)d_out;

    bin_table_kernel<<<(TAB + 255) / 256, 256>>>(rois);
    roi_align_kernel<<<OUT_TOTAL / 256, 256>>>(features, out);
}

// round 3
// speedup vs baseline: 2.1899x; 2.1899x over previous
#include <cuda_runtime.h>

// RoIAlign: features (2,256,8,64,64) f32, rois (512,5) f32
// out (512,256,8,7,7) f32
//
// Kernel 1 (1 block, 512 thr): per-roi geometry params + deterministic
//   per-batch compacted roi lists (ballot prefix scan).
// Kernel 2 (2048 blocks): one block per (batch, ct-pair). Stage both 64x64
//   feature slices in padded SMEM (each feature float read from DRAM exactly
//   once, coalesced), then loop this batch's (roi,bin) pairs doing 4-corner
//   bilinear from SMEM for 2 ct slices at once.

#define C_   256
#define T_   8
#define H_   64
#define W_   64
#define R_   512
#define S_   49                 // 7*7
#define CT_  (C_*T_)            // 2048
#define SLICE (H_*W_)           // 4096 floats
#define PAD_W 65                // row pad: kills cross-row bank aliasing

// per-roi params: {px = x1+0.5*bw, py = y1+0.5*bh, bw, bh signed by batch}
__device__ float4 g_params[R_];
__device__ int    g_list[2 * R_];   // [0..cnt0) batch0, [512..512+cnt1) batch1
__device__ int    g_cnt[2];

__global__ void param_kernel(const float* __restrict__ rois) {
    int r = threadIdx.x;                       // 512 threads, 1 block
    const float* roi = rois + r * 5;
    int   b  = (int)roi[0];
    float x1 = roi[1] * 0.0625f;
    float y1 = roi[2] * 0.0625f;
    float x2 = roi[3] * 0.0625f;
    float y2 = roi[4] * 0.0625f;
    float bw = fmaxf(x2 - x1, 1.0f) * (1.0f / 7.0f);
    float bh = fmaxf(y2 - y1, 1.0f) * (1.0f / 7.0f);
    float px = x1 + 0.5f * bw;
    float py = y1 + 0.5f * bh;
    g_params[r] = make_float4(px, py, bw, b ? -bh : bh);

    // deterministic compaction: rank1 = #(batch1 rois with index < r)
    unsigned ballot = __ballot_sync(0xffffffffu, b != 0);
    int lane = r & 31, warp = r >> 5;
    int within1 = __popc(ballot & ((1u << lane) - 1u));
    __shared__ int wtot[16];
    if (lane == 31) wtot[warp] = __popc(ballot);
    __syncthreads();
    int before1 = 0;
    #pragma unroll
    for (int w = 0; w < 16; w++)
        if (w < warp) before1 += wtot[w];
    int rank1 = before1 + within1;
    int rank0 = r - rank1;
    if (b) g_list[R_ + rank1] = r;
    else   g_list[rank0]      = r;
    if (r == R_ - 1) {
        int tot1 = before1 + __popc(ballot);
        g_cnt[1] = tot1;
        g_cnt[0] = R_ - tot1;
    }
}

__global__ void __launch_bounds__(256) roi_align_kernel(
    const float* __restrict__ features,
    float* __restrict__ out)
{
    __shared__ float sl0[H_ * PAD_W];
    __shared__ float sl1[H_ * PAD_W];

    unsigned z    = blockIdx.x;          // [0, 2048)
    unsigned myb  = z >> 10;             // batch 0/1
    unsigned ct0  = (z & 1023u) << 1;    // even ct of the pair

    // ---- stage 2 slices (2 x 16KB), coalesced LDG.128, padded scalar STS ----
    const float4* src = (const float4*)(features + ((myb << 11) + ct0) * (unsigned)SLICE);
    for (unsigned i = threadIdx.x; i < 2048u; i += 256u) {   // 2048 float4 = 2 slices
        float4 v = __ldg(src + i);
        unsigned w  = i & 1023u;
        unsigned y  = w >> 4;
        unsigned x4 = (w & 15u) << 2;
        float* d = ((i >> 10) ? sl1 : sl0) + y * PAD_W + x4;
        d[0] = v.x; d[1] = v.y; d[2] = v.z; d[3] = v.w;
    }
    __syncthreads();

    // ---- loop this batch's (roi, bin) pairs only (compacted list) ----
    int cnt = g_cnt[myb];
    unsigned nk = (unsigned)cnt * 49u;
    const int* lst = g_list + (myb << 9);

    for (unsigned k = threadIdx.x; k < nk; k += 256u) {
        unsigned q  = k / 49u;
        unsigned s  = k - q * 49u;
        int r = lst[q];
        float4 p = __ldg(&g_params[r]);

        unsigned ph = s / 7u;
        unsigned pw = s - ph * 7u;

        float bh = fabsf(p.w);
        float xs = fminf(fmaxf(fmaf((float)pw, p.z, p.x), 0.0f), 63.0f);
        float ys = fminf(fmaxf(fmaf((float)ph, bh,  p.y), 0.0f), 63.0f);

        float x0f = floorf(xs);
        float y0f = floorf(ys);
        float wx  = xs - x0f;
        float wy  = ys - y0f;
        int x0 = (int)x0f;
        int y0 = (int)y0f;
        int dx = (x0 < 63) ? 1 : 0;
        int dy = (y0 < 63) ? PAD_W : 0;
        int a00 = y0 * PAD_W + x0;

        float omx = 1.0f - wx;
        float omy = 1.0f - wy;
        float w00 = omy * omx;
        float w01 = omy * wx;
        float w10 = wy * omx;
        float w11 = wy * wx;

        float a0 = w00 * sl0[a00];
        a0 = fmaf(w01, sl0[a00 + dx],      a0);
        a0 = fmaf(w10, sl0[a00 + dy],      a0);
        a0 = fmaf(w11, sl0[a00 + dy + dx], a0);

        float a1 = w00 * sl1[a00];
        a1 = fmaf(w01, sl1[a00 + dx],      a1);
        a1 = fmaf(w10, sl1[a00 + dy],      a1);
        a1 = fmaf(w11, sl1[a00 + dy + dx], a1);

        unsigned ob = (unsigned)r * (unsigned)(CT_ * S_) + ct0 * 49u + s;
        out[ob]      = a0;
        out[ob + 49] = a1;
    }
}

extern "C" void kernel_launch(void* const* d_in, const int* in_sizes, int n_in,
                              void* d_out, int out_size) {
    const float* features = (const float*)d_in[0];
    const float* rois     = (const float*)d_in[1];
    float* out            = (float*)d_out;

    param_kernel<<<1, 512>>>(rois);
    roi_align_kernel<<<2048, 256>>>(features, out);
}